// round 5
// baseline (speedup 1.0000x reference)
#include <cuda_runtime.h>

// Problem constants
#define S_   4
#define N_   32768
#define H_   100
#define K_   256
#define MT   64          // n-points per stage-A block
#define NB   (N_ / MT)   // 512 stage-A blocks per s
#define CH2  50          // GEMM2 rows per chunk (2 chunks)
#define CH3  25          // GEMM3 rows per chunk (4 chunks per pass)
#define NT   256         // threads per stage-A block

// stage-A shared memory (floats):
//   hdup[100][128] (h1dup, later h2dup) | Wt[2][6400] | uS[2][64]
#define HD   (H_ * 128)          // 12800
#define BUF  6400
#define SM_FLOATS (HD + 2*BUF + 2*MT)
#define SM_BYTES  (SM_FLOATS * 4)

// Scratch: per-CTA partials (a,b,c,d,e) and per-(s,k) w.
__device__ float g_part[S_ * 5 * NB * K_];   // [s][comp][blk][k]
__device__ float g_w[S_ * K_ * 2];

// ---------------- packed f32x2 helpers (sm_100+) ----------------
static __device__ __forceinline__ unsigned long long pack2(float x, float y) {
    unsigned long long r;
    asm("mov.b64 %0, {%1, %2};" : "=l"(r) : "f"(x), "f"(y));
    return r;
}
static __device__ __forceinline__ void unpack2(unsigned long long p, float &x, float &y) {
    asm("mov.b64 {%0, %1}, %2;" : "=f"(x), "=f"(y) : "l"(p));
}
static __device__ __forceinline__ void ffma2(unsigned long long &d,
                                             unsigned long long a,
                                             unsigned long long b) {
    asm("fma.rn.f32x2 %0, %1, %2, %0;" : "+l"(d) : "l"(a), "l"(b));
}

// ---------------- cp.async helpers ----------------
static __device__ __forceinline__ unsigned smem_u32(const void* p) {
    return (unsigned)__cvta_generic_to_shared(p);
}
static __device__ __forceinline__ void cpa16(unsigned dst, const float* src) {
    asm volatile("cp.async.cg.shared.global [%0], [%1], 16;\n" :: "r"(dst), "l"(src));
}
#define CPA_COMMIT() asm volatile("cp.async.commit_group;\n" ::: "memory")
#define CPA_WAIT0()  asm volatile("cp.async.wait_group 0;\n" ::: "memory")

// ---------------- Stage A ----------------
// 256 threads = 16 (tn: 4 rows each) x 16 (tj).
// GEMM2: 64x128 tile, tj covers 8 cols. GEMM3: two passes; tj covers
// 8 logprec cols (kb+tj*8) and the paired 8 mu cols (256+kb+tj*8).
// Activations live duplicated in smem: hdup[i][2n]=hdup[i][2n+1]=h[i][n],
// so FFMA2 broadcast operands load as natural 64-bit pairs (no MOV packs).
__global__ void __launch_bounds__(NT, 2)
stageA_kernel(const float* __restrict__ U,  const float* __restrict__ W1,
              const float* __restrict__ b1, const float* __restrict__ W2,
              const float* __restrict__ b2, const float* __restrict__ W3,
              const float* __restrict__ b3)
{
    extern __shared__ float sm[];
    float* hdup = sm;                    // [100][128]: h1dup, then h2dup
    float* Wt   = hdup + HD;             // [2][6400]
    float* uS   = Wt + 2 * BUF;          // [2][64]

    const int tid  = threadIdx.x;
    const int tn   = tid & 15;
    const int tj   = tid >> 4;           // 0..15
    const int s    = blockIdx.y;
    const int blk  = blockIdx.x;
    const int n0   = blk * MT;
    const int nloc = tn * 4;

    // Load U tile; kick off W2 chunk 0 staging (rows 0..49, pad cols>=100).
    if (tid < MT) {
        const float* up = U + ((size_t)(s * N_ + n0 + tid) << 1);
        uS[tid]      = up[0];
        uS[MT + tid] = up[1];
    }
    for (int idx = tid; idx < CH2 * 32; idx += NT) {
        int row = idx >> 5, c = (idx & 31) * 4;
        if (c < H_) cpa16(smem_u32(Wt + row * 128 + c), W2 + row * H_ + c);
        else *reinterpret_cast<float4*>(Wt + row * 128 + c) = make_float4(0.f, 0.f, 0.f, 0.f);
    }
    CPA_COMMIT();
    __syncthreads();

    // Layer 1 (duplicated store): hdup[i][2n]=hdup[i][2n+1]=relu(...)
    for (int idx = tid; idx < H_ * MT; idx += NT) {
        int i = idx >> 6, n = idx & 63;
        float v = fmaxf(fmaf(uS[n], W1[i], fmaf(uS[MT + n], W1[H_ + i], b1[i])), 0.f);
        *reinterpret_cast<unsigned long long*>(hdup + i * 128 + 2 * n) = pack2(v, v);
    }

    // ---- GEMM2: h2 = relu(h1 @ W2 + b2), 2 chunks of 50 rows ----
    unsigned long long acc2[4][4];
    #pragma unroll
    for (int r = 0; r < 4; ++r)
        #pragma unroll
        for (int c = 0; c < 4; ++c) acc2[r][c] = 0ULL;

    int cb = 0;
    for (int ch = 0; ch < 2; ++ch) {
        CPA_WAIT0();
        __syncthreads();                 // chunk + h1dup visible
        if (ch == 0) {                   // prefetch chunk 1 (rows 50..99)
            float* dst = Wt + BUF;
            for (int idx = tid; idx < CH2 * 32; idx += NT) {
                int row = idx >> 5, c = (idx & 31) * 4;
                if (c < H_) cpa16(smem_u32(dst + row * 128 + c),
                                  W2 + (size_t)(CH2 + row) * H_ + c);
                else *reinterpret_cast<float4*>(dst + row * 128 + c) = make_float4(0.f, 0.f, 0.f, 0.f);
            }
            CPA_COMMIT();
        }
        const float* buf = Wt + cb * BUF;
        #pragma unroll 10
        for (int i = 0; i < CH2; ++i) {
            const float* ap = hdup + (ch * CH2 + i) * 128 + 2 * nloc;
            ulonglong2 a01 = *reinterpret_cast<const ulonglong2*>(ap);
            ulonglong2 a23 = *reinterpret_cast<const ulonglong2*>(ap + 4);
            const float* bp = buf + i * 128 + tj * 8;
            ulonglong2 b01 = *reinterpret_cast<const ulonglong2*>(bp);
            ulonglong2 b23 = *reinterpret_cast<const ulonglong2*>(bp + 4);
            unsigned long long aa[4] = { a01.x, a01.y, a23.x, a23.y };
            unsigned long long bb[4] = { b01.x, b01.y, b23.x, b23.y };
            #pragma unroll
            for (int r = 0; r < 4; ++r)
                #pragma unroll
                for (int c = 0; c < 4; ++c) ffma2(acc2[r][c], aa[r], bb[c]);
        }
        cb ^= 1;
    }
    // cb == 0 again. Prefetch GEMM3 pass-0 chunk-0 into buf0 (free since ch0).
    for (int idx = tid; idx < CH3 * 64; idx += NT) {
        int row = idx >> 6, c = (idx & 63) * 4;
        int col = (c < 128) ? c : (256 + (c - 128));
        cpa16(smem_u32(Wt + row * 256 + c), W3 + (size_t)row * 512 + col);
    }
    CPA_COMMIT();

    __syncthreads();   // all GEMM2 reads of hdup(h1) done before overwrite

    // GEMM2 epilogue: +b2, relu, store h2 DUPLICATED into hdup (j < 100)
    #pragma unroll
    for (int c2 = 0; c2 < 4; ++c2) {
        int j0 = tj * 8 + c2 * 2;
        float bj0 = (j0     < H_) ? b2[j0]     : 0.f;
        float bj1 = (j0 + 1 < H_) ? b2[j0 + 1] : 0.f;
        #pragma unroll
        for (int r = 0; r < 4; ++r) {
            float v0, v1; unpack2(acc2[r][c2], v0, v1);
            float h0 = fmaxf(v0 + bj0, 0.f), h1v = fmaxf(v1 + bj1, 0.f);
            if (j0 < H_)
                *reinterpret_cast<unsigned long long*>(hdup + j0 * 128 + 2 * (nloc + r)) = pack2(h0, h0);
            if (j0 + 1 < H_)
                *reinterpret_cast<unsigned long long*>(hdup + (j0 + 1) * 128 + 2 * (nloc + r)) = pack2(h1v, h1v);
        }
    }

    // ---- GEMM3: two passes; logprec cols [kb,kb+128) + mu cols [256+kb,...) ----
    for (int p = 0; p < 2; ++p) {
        const int kb = p * 128;

        unsigned long long aLP[4][4], aMU[4][4];
        #pragma unroll
        for (int r = 0; r < 4; ++r)
            #pragma unroll
            for (int c = 0; c < 4; ++c) { aLP[r][c] = 0ULL; aMU[r][c] = 0ULL; }

        for (int ch = 0; ch < 4; ++ch) {
            CPA_WAIT0();
            __syncthreads();             // chunk visible; epilogue hdup writes ordered
            if (ch < 3) {                // prefetch next chunk of this pass
                float* dst = Wt + (cb ^ 1) * BUF;
                for (int idx = tid; idx < CH3 * 64; idx += NT) {
                    int row = idx >> 6, c = (idx & 63) * 4;
                    int col = (c < 128) ? (kb + c) : (256 + kb + (c - 128));
                    cpa16(smem_u32(dst + row * 256 + c),
                          W3 + (size_t)((ch + 1) * CH3 + row) * 512 + col);
                }
                CPA_COMMIT();
            } else if (p == 0) {         // prefetch pass-1 chunk-0
                float* dst = Wt + (cb ^ 1) * BUF;
                for (int idx = tid; idx < CH3 * 64; idx += NT) {
                    int row = idx >> 6, c = (idx & 63) * 4;
                    int col = (c < 128) ? (128 + c) : (256 + 128 + (c - 128));
                    cpa16(smem_u32(dst + row * 256 + c), W3 + (size_t)row * 512 + col);
                }
                CPA_COMMIT();
            }
            const float* buf = Wt + cb * BUF;
            #pragma unroll 5
            for (int i = 0; i < CH3; ++i) {
                const float* ap = hdup + (ch * CH3 + i) * 128 + 2 * nloc;
                ulonglong2 a01 = *reinterpret_cast<const ulonglong2*>(ap);
                ulonglong2 a23 = *reinterpret_cast<const ulonglong2*>(ap + 4);
                const float* bl = buf + i * 256 + tj * 8;
                ulonglong2 l01 = *reinterpret_cast<const ulonglong2*>(bl);
                ulonglong2 l23 = *reinterpret_cast<const ulonglong2*>(bl + 4);
                ulonglong2 m01 = *reinterpret_cast<const ulonglong2*>(bl + 128);
                ulonglong2 m23 = *reinterpret_cast<const ulonglong2*>(bl + 132);
                unsigned long long aa[4] = { a01.x, a01.y, a23.x, a23.y };
                unsigned long long bL[4] = { l01.x, l01.y, l23.x, l23.y };
                unsigned long long bM[4] = { m01.x, m01.y, m23.x, m23.y };
                #pragma unroll
                for (int r = 0; r < 4; ++r) {
                    #pragma unroll
                    for (int c = 0; c < 4; ++c) ffma2(aLP[r][c], aa[r], bL[c]);
                    #pragma unroll
                    for (int c = 0; c < 4; ++c) ffma2(aMU[r][c], aa[r], bM[c]);
                }
            }
            cb ^= 1;
        }

        // fused epilogue: prec = exp(lp + b3), pm = prec*(mu + b3'), reduce a..e
        float b3l[8], b3m[8];
        #pragma unroll
        for (int c = 0; c < 8; ++c) {
            b3l[c] = b3[kb + tj * 8 + c];
            b3m[c] = b3[256 + kb + tj * 8 + c];
        }
        float pa[8], pb_[8], pc_[8], pd[8], pe[8];
        #pragma unroll
        for (int c = 0; c < 8; ++c) { pa[c]=0.f; pb_[c]=0.f; pc_[c]=0.f; pd[c]=0.f; pe[c]=0.f; }

        #pragma unroll
        for (int r = 0; r < 4; ++r) {
            float u0 = uS[nloc + r], u1 = uS[MT + nloc + r];
            float uu00 = u0 * u0, uu01 = u0 * u1, uu11 = u1 * u1;
            #pragma unroll
            for (int c2 = 0; c2 < 4; ++c2) {
                float l0, l1, m0, m1;
                unpack2(aLP[r][c2], l0, l1);
                unpack2(aMU[r][c2], m0, m1);
                int c = c2 * 2;
                float p0 = __expf(l0 + b3l[c]);
                float p1 = __expf(l1 + b3l[c + 1]);
                float pm0 = p0 * (m0 + b3m[c]);
                float pm1 = p1 * (m1 + b3m[c + 1]);
                pa[c]     += p0 * uu00; pb_[c]     += p0 * uu01; pc_[c]     += p0 * uu11;
                pd[c]     += pm0 * u0;  pe[c]      += pm0 * u1;
                pa[c + 1] += p1 * uu00; pb_[c + 1] += p1 * uu01; pc_[c + 1] += p1 * uu11;
                pd[c + 1] += pm1 * u0;  pe[c + 1]  += pm1 * u1;
            }
        }
        #pragma unroll
        for (int c = 0; c < 8; ++c)
            #pragma unroll
            for (int off = 8; off; off >>= 1) {
                pa[c]  += __shfl_xor_sync(0xffffffffu, pa[c],  off);
                pb_[c] += __shfl_xor_sync(0xffffffffu, pb_[c], off);
                pc_[c] += __shfl_xor_sync(0xffffffffu, pc_[c], off);
                pd[c]  += __shfl_xor_sync(0xffffffffu, pd[c],  off);
                pe[c]  += __shfl_xor_sync(0xffffffffu, pe[c],  off);
            }
        if (tn == 0) {
            int kbase = kb + tj * 8;
            size_t base = ((size_t)s * 5 * NB + blk) * K_ + kbase;   // comp stride NB*K_
            #pragma unroll
            for (int c = 0; c < 8; ++c) {
                g_part[base + c]                 = pa[c];
                g_part[base + (size_t)NB*K_   + c] = pb_[c];
                g_part[base + (size_t)NB*K_*2 + c] = pc_[c];
                g_part[base + (size_t)NB*K_*3 + c] = pd[c];
                g_part[base + (size_t)NB*K_*4 + c] = pe[c];
            }
        }
    }
}

// ---------------- Stage B: reduce partials, 2x2 posterior + KL ----------------
__global__ void stageB_kernel(const float* __restrict__ eps, float* __restrict__ kl_out)
{
    __shared__ float red[256];
    const int s = blockIdx.x;
    const int k = threadIdx.x;

    const float* p0 = g_part + ((size_t)s * 5 * NB) * K_ + k;
    float A = 0.f, B = 0.f, C = 0.f, dd = 0.f, ee = 0.f;
    #pragma unroll 4
    for (int b = 0; b < NB; ++b) {
        size_t o = (size_t)b * K_;
        A  += p0[o];
        B  += p0[(size_t)NB*K_   + o];
        C  += p0[(size_t)NB*K_*2 + o];
        dd += p0[(size_t)NB*K_*3 + o];
        ee += p0[(size_t)NB*K_*4 + o];
    }
    A += 1.f;  C += 1.f;                  // q_prec = UTLU + I (PRIOR_VAR = 1)

    float det = A * C - B * B;
    float inv = 1.f / det;
    float c00 = C * inv, c01 = -B * inv, c11 = A * inv;   // q_cov
    float qm0 = c00 * dd + c01 * ee;                      // q_mu
    float qm1 = c01 * dd + c11 * ee;

    float l00 = sqrtf(c00);                               // Lc = chol(q_cov)
    float l10 = c01 / l00;
    float l11 = sqrtf(fmaxf(c11 - l10 * l10, 0.f));

    float e0 = eps[(s * K_ + k) * 2];
    float e1 = eps[(s * K_ + k) * 2 + 1];
    g_w[(s * K_ + k) * 2]     = qm0 + l00 * e0;
    g_w[(s * K_ + k) * 2 + 1] = qm1 + l10 * e0 + l11 * e1;

    float kl = 0.5f * ((c00 + c11) + (qm0 * qm0 + qm1 * qm1) - 2.f + logf(det));
    red[k] = kl;
    __syncthreads();
    for (int off = 128; off; off >>= 1) {
        if (k < off) red[k] += red[k + off];
        __syncthreads();
    }
    if (k == 0) kl_out[s] = red[0];
}

// ---------------- Stage C: out_U = relu(U . w), bandwidth bound ----------------
__global__ void __launch_bounds__(256)
stageC_kernel(const float* __restrict__ U, float* __restrict__ out)
{
    __shared__ float w0s[K_], w1s[K_], u0s[64], u1s[64];
    const int s  = blockIdx.y;
    const int n0 = blockIdx.x * 64;
    const int tid = threadIdx.x;

    w0s[tid] = g_w[(s * K_ + tid) * 2];
    w1s[tid] = g_w[(s * K_ + tid) * 2 + 1];
    if (tid < 64) {
        const float* up = U + ((size_t)(s * N_ + n0 + tid) << 1);
        u0s[tid] = up[0];
        u1s[tid] = up[1];
    }
    __syncthreads();

    const int kq = tid & 63;
    const int r  = tid >> 6;
    #pragma unroll
    for (int nn = 0; nn < 16; ++nn) {
        int nl = nn * 4 + r;
        float u0 = u0s[nl], u1 = u1s[nl];
        int k = kq * 4;
        float4 o;
        o.x = fmaxf(fmaf(u0, w0s[k],     u1 * w1s[k]),     0.f);
        o.y = fmaxf(fmaf(u0, w0s[k + 1], u1 * w1s[k + 1]), 0.f);
        o.z = fmaxf(fmaf(u0, w0s[k + 2], u1 * w1s[k + 2]), 0.f);
        o.w = fmaxf(fmaf(u0, w0s[k + 3], u1 * w1s[k + 3]), 0.f);
        reinterpret_cast<float4*>(out)[(((size_t)(s * N_ + n0 + nl)) * K_ + k) >> 2] = o;
    }
}

// ---------------- launch ----------------
extern "C" void kernel_launch(void* const* d_in, const int* in_sizes, int n_in,
                              void* d_out, int out_size)
{
    const float* U   = (const float*)d_in[0];
    const float* eps = (const float*)d_in[1];
    const float* W1  = (const float*)d_in[2];
    const float* b1  = (const float*)d_in[3];
    const float* W2  = (const float*)d_in[4];
    const float* b2  = (const float*)d_in[5];
    const float* W3  = (const float*)d_in[6];
    const float* b3  = (const float*)d_in[7];
    float* out = (float*)d_out;

    cudaFuncSetAttribute((const void*)stageA_kernel,
                         cudaFuncAttributeMaxDynamicSharedMemorySize, SM_BYTES);

    stageA_kernel<<<dim3(NB, S_), NT, SM_BYTES>>>(U, W1, b1, W2, b2, W3, b3);
    stageB_kernel<<<S_, 256>>>(eps, out + (out_size - S_));
    stageC_kernel<<<dim3(N_ / 64, S_), 256>>>(U, out);
}